// round 4
// baseline (speedup 1.0000x reference)
#include <cuda_runtime.h>
#include <cstdint>
#include <math.h>

#define N_NODES 50000
#define N_EDGES 800000
#define IN_DIM 128
#define EDGE_DIM 16
#define HIDDEN 128
#define N_LAYERS 3
#define N_GRAPHS 256

typedef unsigned long long u64;

// ---------------- scratch (device globals: allocation-free) ----------------
__device__ float g_h[(size_t)N_NODES * HIDDEN];        // node hidden state
__device__ float g_agg[(size_t)N_NODES * HIDDEN];      // scatter-add target
__device__ float g_gi[(size_t)N_NODES * 3 * HIDDEN];   // GRU input gates
__device__ float g_gh[(size_t)N_NODES * 3 * HIDDEN];   // GRU hidden gates
__device__ float g_zsum[N_GRAPHS * HIDDEN];
__device__ unsigned g_zmax[N_GRAPHS * HIDDEN];
__device__ float g_cnt[N_GRAPHS];

// ---------------- packed fp32x2 helpers (FFMA2: 2 MACs/inst) ----------------
__device__ __forceinline__ u64 pack2(float x, float y) {
    u64 r; asm("mov.b64 %0,{%1,%2};" : "=l"(r) : "f"(x), "f"(y)); return r;
}
__device__ __forceinline__ float2 unpack2(u64 v) {
    float2 f; asm("mov.b64 {%0,%1},%2;" : "=f"(f.x), "=f"(f.y) : "l"(v)); return f;
}
__device__ __forceinline__ void fma2(u64& d, u64 a, u64 b) {
    asm("fma.rn.f32x2 %0,%1,%2,%0;" : "+l"(d) : "l"(a), "l"(b));
}

// order-preserving float<->uint for atomicMax
__device__ __forceinline__ unsigned fenc(float f) {
    unsigned u = __float_as_uint(f);
    return (u & 0x80000000u) ? ~u : (u | 0x80000000u);
}
__device__ __forceinline__ float fdec(unsigned u) {
    return __uint_as_float((u & 0x80000000u) ? (u ^ 0x80000000u) : ~u);
}

// ---------------- smem sizes ----------------
#define EDGE_SMEM ((144*128 + 128*128 + 64*144 + 64*128) * 4)   // 208896 B
#define LIN_SMEM  ((128*128 + 32*128) * 4)                       // 81920 B
#define GRU_SMEM  ((128*132 + 32*128) * 4)                       // 83968 B

// ============================================================================
// lin_in: h = relu(x @ W + b), W [128,128] row-major [k][n]
// 256 threads, 32-row tiles, tile-stride loop
// ============================================================================
__global__ __launch_bounds__(256, 2) void lin_in_kernel(
    const float* __restrict__ x, const float* __restrict__ W,
    const float* __restrict__ b)
{
    extern __shared__ float sm[];
    float* sW = sm;              // [128][128]
    float* sA = sW + 128 * 128;  // [32][128]
    const int tid = threadIdx.x;
    for (int i = tid; i < 128 * 128; i += 256) sW[i] = W[i];
    const int warp = tid >> 5, lane = tid & 31;
    const int r0 = warp * 4, c0 = lane * 4;
    const u64 bp0 = pack2(b[c0], b[c0 + 1]), bp1 = pack2(b[c0 + 2], b[c0 + 3]);
    __syncthreads();

    const int ntiles = (N_NODES + 31) / 32;
    for (int t = blockIdx.x; t < ntiles; t += gridDim.x) {
        const int n0 = t * 32;
        {   // load A tile: 8 threads per row
            const int lr = tid >> 3, sub = tid & 7;
            const int n = n0 + lr;
            float4* ap = (float4*)(sA + lr * 128);
            if (n < N_NODES) {
                const float4* xp = (const float4*)(x + (size_t)n * 128);
                #pragma unroll
                for (int i = 0; i < 4; i++) ap[sub * 4 + i] = xp[sub * 4 + i];
            } else {
                float4 z = make_float4(0.f, 0.f, 0.f, 0.f);
                #pragma unroll
                for (int i = 0; i < 4; i++) ap[sub * 4 + i] = z;
            }
        }
        __syncthreads();
        u64 acc[4][2];
        #pragma unroll
        for (int i = 0; i < 4; i++) { acc[i][0] = bp0; acc[i][1] = bp1; }
        const float* A0 = sA + (r0 + 0) * 128;
        const float* A1 = sA + (r0 + 1) * 128;
        const float* A2 = sA + (r0 + 2) * 128;
        const float* A3 = sA + (r0 + 3) * 128;
        #pragma unroll 4
        for (int k = 0; k < 128; k++) {
            const ulonglong2 bv = *(const ulonglong2*)(sW + k * 128 + c0);
            u64 p;
            p = pack2(A0[k], A0[k]); fma2(acc[0][0], p, bv.x); fma2(acc[0][1], p, bv.y);
            p = pack2(A1[k], A1[k]); fma2(acc[1][0], p, bv.x); fma2(acc[1][1], p, bv.y);
            p = pack2(A2[k], A2[k]); fma2(acc[2][0], p, bv.x); fma2(acc[2][1], p, bv.y);
            p = pack2(A3[k], A3[k]); fma2(acc[3][0], p, bv.x); fma2(acc[3][1], p, bv.y);
        }
        #pragma unroll
        for (int i = 0; i < 4; i++) {
            const int n = n0 + r0 + i;
            if (n < N_NODES) {
                float2 x0 = unpack2(acc[i][0]), x1 = unpack2(acc[i][1]);
                *(float4*)(g_h + (size_t)n * 128 + c0) =
                    make_float4(fmaxf(x0.x, 0.f), fmaxf(x0.y, 0.f),
                                fmaxf(x1.x, 0.f), fmaxf(x1.y, 0.f));
            }
        }
        __syncthreads();
    }
}

// ============================================================================
// fused edge message kernel:
//   m = relu([h[src], e_attr] @ W1 + b1) @ W2 + b2 ; atomicAdd into agg[dst]
// 512 threads, 64-edge tiles, W1+W2 resident in SMEM (~138 KB)
// ============================================================================
__global__ __launch_bounds__(512, 1) void edge_msg_kernel(
    const int* __restrict__ src, const int* __restrict__ dst,
    const float* __restrict__ edge_attr,
    const float* __restrict__ W1, const float* __restrict__ b1,
    const float* __restrict__ W2, const float* __restrict__ b2)
{
    extern __shared__ float sm[];
    float* sW1 = sm;               // [144][128]
    float* sW2 = sW1 + 144 * 128;  // [128][128]
    float* sA  = sW2 + 128 * 128;  // [64][144]
    float* sH  = sA + 64 * 144;    // [64][128]
    const int tid = threadIdx.x;
    for (int i = tid; i < 144 * 128; i += 512) sW1[i] = W1[i];
    for (int i = tid; i < 128 * 128; i += 512) sW2[i] = W2[i];
    const int warp = tid >> 5, lane = tid & 31;
    const int r0 = warp * 4, c0 = lane * 4;
    const u64 b1p0 = pack2(b1[c0], b1[c0 + 1]), b1p1 = pack2(b1[c0 + 2], b1[c0 + 3]);
    const u64 b2p0 = pack2(b2[c0], b2[c0 + 1]), b2p1 = pack2(b2[c0 + 2], b2[c0 + 3]);
    __syncthreads();

    const int ntiles = N_EDGES / 64;   // 12500 exact
    for (int t = blockIdx.x; t < ntiles; t += gridDim.x) {
        const int e0 = t * 64;
        {   // gather inputs: 8 threads per edge
            const int le = tid >> 3, sub = tid & 7;
            const int e = e0 + le;
            const int s = src[e];
            const float4* hp = (const float4*)(g_h + (size_t)s * 128);
            float4* ap = (float4*)(sA + le * 144);
            #pragma unroll
            for (int i = 0; i < 4; i++) ap[sub * 4 + i] = hp[sub * 4 + i];
            const float2 ea = *(const float2*)(edge_attr + (size_t)e * 16 + sub * 2);
            sA[le * 144 + 128 + sub * 2]     = ea.x;
            sA[le * 144 + 128 + sub * 2 + 1] = ea.y;
        }
        __syncthreads();

        // GEMM1: hid = relu(A[64,144] @ W1 + b1)
        u64 acc[4][2];
        #pragma unroll
        for (int i = 0; i < 4; i++) { acc[i][0] = b1p0; acc[i][1] = b1p1; }
        {
            const float* A0 = sA + (r0 + 0) * 144;
            const float* A1 = sA + (r0 + 1) * 144;
            const float* A2 = sA + (r0 + 2) * 144;
            const float* A3 = sA + (r0 + 3) * 144;
            #pragma unroll 4
            for (int k = 0; k < 144; k++) {
                const ulonglong2 bv = *(const ulonglong2*)(sW1 + k * 128 + c0);
                u64 p;
                p = pack2(A0[k], A0[k]); fma2(acc[0][0], p, bv.x); fma2(acc[0][1], p, bv.y);
                p = pack2(A1[k], A1[k]); fma2(acc[1][0], p, bv.x); fma2(acc[1][1], p, bv.y);
                p = pack2(A2[k], A2[k]); fma2(acc[2][0], p, bv.x); fma2(acc[2][1], p, bv.y);
                p = pack2(A3[k], A3[k]); fma2(acc[3][0], p, bv.x); fma2(acc[3][1], p, bv.y);
            }
        }
        #pragma unroll
        for (int i = 0; i < 4; i++) {
            float2 x0 = unpack2(acc[i][0]), x1 = unpack2(acc[i][1]);
            *(float4*)(sH + (r0 + i) * 128 + c0) =
                make_float4(fmaxf(x0.x, 0.f), fmaxf(x0.y, 0.f),
                            fmaxf(x1.x, 0.f), fmaxf(x1.y, 0.f));
        }
        __syncthreads();

        // GEMM2: m = hid[64,128] @ W2 + b2
        #pragma unroll
        for (int i = 0; i < 4; i++) { acc[i][0] = b2p0; acc[i][1] = b2p1; }
        {
            const float* H0 = sH + (r0 + 0) * 128;
            const float* H1 = sH + (r0 + 1) * 128;
            const float* H2 = sH + (r0 + 2) * 128;
            const float* H3 = sH + (r0 + 3) * 128;
            #pragma unroll 4
            for (int k = 0; k < 128; k++) {
                const ulonglong2 bv = *(const ulonglong2*)(sW2 + k * 128 + c0);
                u64 p;
                p = pack2(H0[k], H0[k]); fma2(acc[0][0], p, bv.x); fma2(acc[0][1], p, bv.y);
                p = pack2(H1[k], H1[k]); fma2(acc[1][0], p, bv.x); fma2(acc[1][1], p, bv.y);
                p = pack2(H2[k], H2[k]); fma2(acc[2][0], p, bv.x); fma2(acc[2][1], p, bv.y);
                p = pack2(H3[k], H3[k]); fma2(acc[3][0], p, bv.x); fma2(acc[3][1], p, bv.y);
            }
        }
        // scatter-add to agg[dst]
        #pragma unroll
        for (int i = 0; i < 4; i++) {
            const int e = e0 + r0 + i;
            const int d = dst[e];
            float* o = g_agg + (size_t)d * 128 + c0;
            float2 x0 = unpack2(acc[i][0]), x1 = unpack2(acc[i][1]);
            atomicAdd(o + 0, x0.x);
            atomicAdd(o + 1, x0.y);
            atomicAdd(o + 2, x1.x);
            atomicAdd(o + 3, x1.y);
        }
        __syncthreads();
    }
}

// ============================================================================
// GRU gemms: gi = agg @ wih^T + bih ; gh = h @ whh^T + bhh
// grid.y in [0,6): which = y/3 (0:gi, 1:gh), gate = y%3. W chunk transposed to
// smem [k][j] with pad-132 stride.
// ============================================================================
__global__ __launch_bounds__(256, 2) void gru_gemm_kernel(
    const float* __restrict__ wih, const float* __restrict__ whh,
    const float* __restrict__ bih, const float* __restrict__ bhh)
{
    extern __shared__ float sm[];
    float* sW = sm;              // [128][132] transposed chunk
    float* sA = sW + 128 * 132;  // [32][128]
    const int which = blockIdx.y / 3;
    const int gate  = blockIdx.y % 3;
    const float* W    = (which ? whh : wih) + (size_t)gate * 128 * 128;
    const float* bias = (which ? bhh : bih) + gate * 128;
    const float* A    = which ? g_h : g_agg;
    float* out        = which ? g_gh : g_gi;

    const int tid = threadIdx.x;
    for (int i = tid; i < 128 * 128; i += 256) {
        int j = i >> 7, k = i & 127;
        sW[k * 132 + j] = W[i];     // W[j*128+k] -> sW[k][j]
    }
    const int warp = tid >> 5, lane = tid & 31;
    const int r0 = warp * 4, c0 = lane * 4;
    const u64 bp0 = pack2(bias[c0], bias[c0 + 1]), bp1 = pack2(bias[c0 + 2], bias[c0 + 3]);
    __syncthreads();

    const int ntiles = (N_NODES + 31) / 32;
    for (int t = blockIdx.x; t < ntiles; t += gridDim.x) {
        const int n0 = t * 32;
        {
            const int lr = tid >> 3, sub = tid & 7;
            const int n = n0 + lr;
            float4* ap = (float4*)(sA + lr * 128);
            if (n < N_NODES) {
                const float4* xp = (const float4*)(A + (size_t)n * 128);
                #pragma unroll
                for (int i = 0; i < 4; i++) ap[sub * 4 + i] = xp[sub * 4 + i];
            } else {
                float4 z = make_float4(0.f, 0.f, 0.f, 0.f);
                #pragma unroll
                for (int i = 0; i < 4; i++) ap[sub * 4 + i] = z;
            }
        }
        __syncthreads();
        u64 acc[4][2];
        #pragma unroll
        for (int i = 0; i < 4; i++) { acc[i][0] = bp0; acc[i][1] = bp1; }
        const float* A0 = sA + (r0 + 0) * 128;
        const float* A1 = sA + (r0 + 1) * 128;
        const float* A2 = sA + (r0 + 2) * 128;
        const float* A3 = sA + (r0 + 3) * 128;
        #pragma unroll 4
        for (int k = 0; k < 128; k++) {
            const ulonglong2 bv = *(const ulonglong2*)(sW + k * 132 + c0);
            u64 p;
            p = pack2(A0[k], A0[k]); fma2(acc[0][0], p, bv.x); fma2(acc[0][1], p, bv.y);
            p = pack2(A1[k], A1[k]); fma2(acc[1][0], p, bv.x); fma2(acc[1][1], p, bv.y);
            p = pack2(A2[k], A2[k]); fma2(acc[2][0], p, bv.x); fma2(acc[2][1], p, bv.y);
            p = pack2(A3[k], A3[k]); fma2(acc[3][0], p, bv.x); fma2(acc[3][1], p, bv.y);
        }
        #pragma unroll
        for (int i = 0; i < 4; i++) {
            const int n = n0 + r0 + i;
            if (n < N_NODES) {
                float2 x0 = unpack2(acc[i][0]), x1 = unpack2(acc[i][1]);
                *(float4*)(out + (size_t)n * 384 + gate * 128 + c0) =
                    make_float4(x0.x, x0.y, x1.x, x1.y);
            }
        }
        __syncthreads();
    }
}

// ============================================================================
// fused GRU gates + BatchNorm + residual
// ============================================================================
__global__ void gru_gate_kernel(
    const float* __restrict__ gamma, const float* __restrict__ beta,
    const float* __restrict__ mean, const float* __restrict__ var)
{
    const int idx = blockIdx.x * blockDim.x + threadIdx.x;
    if (idx >= N_NODES * HIDDEN) return;
    const int c = idx & 127;
    const size_t n = (size_t)(idx >> 7);
    const float* gi = g_gi + n * 384;
    const float* gh = g_gh + n * 384;
    const float hv = g_h[idx];
    const float r = 1.f / (1.f + expf(-(gi[c] + gh[c])));
    const float z = 1.f / (1.f + expf(-(gi[128 + c] + gh[128 + c])));
    const float nn = tanhf(gi[256 + c] + r * gh[256 + c]);
    const float hnew = (1.f - z) * nn + z * hv;
    const float bn = (hnew - mean[c]) * rsqrtf(var[c] + 1e-5f) * gamma[c] + beta[c];
    g_h[idx] = hv + bn;
}

// ---------------- aux kernels ----------------
__global__ void zero_agg_kernel() {
    const int idx = blockIdx.x * blockDim.x + threadIdx.x;
    if (idx < N_NODES * HIDDEN / 4)
        ((float4*)g_agg)[idx] = make_float4(0.f, 0.f, 0.f, 0.f);
}

__global__ void init_readout_kernel() {
    const int idx = blockIdx.x * blockDim.x + threadIdx.x;
    if (idx < N_GRAPHS * HIDDEN) { g_zsum[idx] = 0.f; g_zmax[idx] = 0x00800000u; }
    if (idx < N_GRAPHS) g_cnt[idx] = 0.f;
}

__global__ void seg_reduce_kernel(const int* __restrict__ batch) {
    const int gid = blockIdx.x * blockDim.x + threadIdx.x;   // N_NODES*32
    if (gid >= N_NODES * 32) return;
    const int n = gid >> 5, q = gid & 31;
    const int g = batch[n];
    const float4 hv = *(const float4*)(g_h + (size_t)n * 128 + q * 4);
    float* zs = g_zsum + g * 128 + q * 4;
    atomicAdd(zs + 0, hv.x); atomicAdd(zs + 1, hv.y);
    atomicAdd(zs + 2, hv.z); atomicAdd(zs + 3, hv.w);
    unsigned* zm = g_zmax + g * 128 + q * 4;
    atomicMax(zm + 0, fenc(hv.x)); atomicMax(zm + 1, fenc(hv.y));
    atomicMax(zm + 2, fenc(hv.z)); atomicMax(zm + 3, fenc(hv.w));
    if (q == 0) atomicAdd(g_cnt + g, 1.f);
}

__global__ void readout_kernel(const float* __restrict__ ro_w,
                               const float* __restrict__ ro_b,
                               float* __restrict__ out)
{
    __shared__ float sbuf[256];
    const int g = blockIdx.x, j = threadIdx.x;   // 128 threads
    const float c = g_cnt[g];
    const float inv = 1.f / fmaxf(c, 1.f);
    sbuf[j]       = g_zsum[g * 128 + j] * inv;
    sbuf[128 + j] = (c > 0.f) ? fdec(g_zmax[g * 128 + j]) : 0.f;
    __syncthreads();
    float acc = ro_b[j];
    #pragma unroll 8
    for (int k = 0; k < 256; k++) acc = fmaf(sbuf[k], ro_w[k * 128 + j], acc);
    out[g * 128 + j] = fmaxf(acc, 0.f);
}

// ============================================================================
extern "C" void kernel_launch(void* const* d_in, const int* in_sizes, int n_in,
                              void* d_out, int out_size)
{
    // setup_inputs order; n_graphs (scalar) may or may not appear as input 4
    const int shift = (in_sizes[4] == 1) ? 1 : 0;
    const float* x         = (const float*)d_in[0];
    const int*   edge_idx  = (const int*)  d_in[1];
    const float* edge_attr = (const float*)d_in[2];
    const int*   batch     = (const int*)  d_in[3];
    const float* lin_in_w  = (const float*)d_in[4 + shift];
    const float* lin_in_b  = (const float*)d_in[5 + shift];
    const float* msg_w1    = (const float*)d_in[6 + shift];
    const float* msg_b1    = (const float*)d_in[7 + shift];
    const float* msg_w2    = (const float*)d_in[8 + shift];
    const float* msg_b2    = (const float*)d_in[9 + shift];
    const float* bn_gamma  = (const float*)d_in[10 + shift];
    const float* bn_beta   = (const float*)d_in[11 + shift];
    const float* bn_mean   = (const float*)d_in[12 + shift];
    const float* bn_var    = (const float*)d_in[13 + shift];
    const float* gru_wih   = (const float*)d_in[14 + shift];
    const float* gru_whh   = (const float*)d_in[15 + shift];
    const float* gru_bih   = (const float*)d_in[16 + shift];
    const float* gru_bhh   = (const float*)d_in[17 + shift];
    const float* ro_w      = (const float*)d_in[18 + shift];
    const float* ro_b      = (const float*)d_in[19 + shift];
    float* out = (float*)d_out;

    static bool inited = false;
    if (!inited) {
        cudaFuncSetAttribute(edge_msg_kernel, cudaFuncAttributeMaxDynamicSharedMemorySize, EDGE_SMEM);
        cudaFuncSetAttribute(lin_in_kernel,   cudaFuncAttributeMaxDynamicSharedMemorySize, LIN_SMEM);
        cudaFuncSetAttribute(gru_gemm_kernel, cudaFuncAttributeMaxDynamicSharedMemorySize, GRU_SMEM);
        inited = true;
    }

    const int* src = edge_idx;
    const int* dst = edge_idx + N_EDGES;

    lin_in_kernel<<<296, 256, LIN_SMEM>>>(x, lin_in_w, lin_in_b);

    for (int l = 0; l < N_LAYERS; l++) {
        zero_agg_kernel<<<(N_NODES * HIDDEN / 4 + 255) / 256, 256>>>();
        edge_msg_kernel<<<148, 512, EDGE_SMEM>>>(
            src, dst, edge_attr,
            msg_w1 + (size_t)l * 144 * 128, msg_b1 + l * 128,
            msg_w2 + (size_t)l * 128 * 128, msg_b2 + l * 128);
        gru_gemm_kernel<<<dim3(296, 6), 256, GRU_SMEM>>>(
            gru_wih + (size_t)l * 384 * 128, gru_whh + (size_t)l * 384 * 128,
            gru_bih + l * 384, gru_bhh + l * 384);
        gru_gate_kernel<<<(N_NODES * HIDDEN + 255) / 256, 256>>>(
            bn_gamma + l * 128, bn_beta + l * 128, bn_mean + l * 128, bn_var + l * 128);
    }

    init_readout_kernel<<<(N_GRAPHS * HIDDEN + 255) / 256, 256>>>();
    seg_reduce_kernel<<<(N_NODES * 32 + 255) / 256, 256>>>(batch);
    readout_kernel<<<N_GRAPHS, 128>>>(ro_w, ro_b, out);
}

// round 8
// speedup vs baseline: 1.0239x; 1.0239x over previous
#include <cuda_runtime.h>
#include <cuda_bf16.h>
#include <cstdint>
#include <math.h>

#define N_NODES 50000
#define N_EDGES 800000
#define IN_DIM 128
#define EDGE_DIM 16
#define HIDDEN 128
#define N_LAYERS 3
#define N_GRAPHS 256

typedef unsigned long long u64;

// ---------------- scratch (device globals: allocation-free) ----------------
__device__ float g_h[(size_t)N_NODES * HIDDEN];        // node hidden state
__device__ float g_agg[(size_t)N_NODES * HIDDEN];      // scatter-add target
__device__ float g_gi[(size_t)N_NODES * 3 * HIDDEN];   // GRU input gates
__device__ float g_gh[(size_t)N_NODES * 3 * HIDDEN];   // GRU hidden gates
__device__ float g_zsum[N_GRAPHS * HIDDEN];
__device__ unsigned g_zmax[N_GRAPHS * HIDDEN];
__device__ float g_cnt[N_GRAPHS];

// ---------------- packed fp32x2 helpers (FFMA2: 2 MACs/inst) ----------------
__device__ __forceinline__ u64 pack2(float x, float y) {
    u64 r; asm("mov.b64 %0,{%1,%2};" : "=l"(r) : "f"(x), "f"(y)); return r;
}
__device__ __forceinline__ float2 unpack2(u64 v) {
    float2 f; asm("mov.b64 {%0,%1},%2;" : "=f"(f.x), "=f"(f.y) : "l"(v)); return f;
}
__device__ __forceinline__ void fma2(u64& d, u64 a, u64 b) {
    asm("fma.rn.f32x2 %0,%1,%2,%0;" : "+l"(d) : "l"(a), "l"(b));
}

// order-preserving float<->uint for atomicMax
__device__ __forceinline__ unsigned fenc(float f) {
    unsigned u = __float_as_uint(f);
    return (u & 0x80000000u) ? ~u : (u | 0x80000000u);
}
__device__ __forceinline__ float fdec(unsigned u) {
    return __uint_as_float((u & 0x80000000u) ? (u ^ 0x80000000u) : ~u);
}

// ---------------- smem sizes ----------------
#define EDGE_SMEM ((144*128 + 128*128 + 64*144 + 64*128) * 4)   // 208896 B
#define LIN_SMEM  ((128*128 + 64*128) * 4)                       // 98304 B
#define GRU_SMEM  ((128*132 + 64*128) * 4)                       // 100352 B

// ============================================================================
// lin_in: h = relu(x @ W + b), W [128,128] row-major [k][n]
// 256 threads = 8 warps; tile = 64 rows; warp: 8 rows x 128 cols;
// thread: 8 rows x 4 cols. A loaded as broadcast float4 per 4-k block.
// ============================================================================
__global__ __launch_bounds__(256, 2) void lin_in_kernel(
    const float* __restrict__ x, const float* __restrict__ W,
    const float* __restrict__ b)
{
    extern __shared__ float sm[];
    float* sW = sm;              // [128][128]
    float* sA = sW + 128 * 128;  // [64][128]
    const int tid = threadIdx.x;
    for (int i = tid; i < 128 * 128; i += 256) sW[i] = W[i];
    const int warp = tid >> 5, lane = tid & 31;
    const int r0 = warp * 8, c0 = lane * 4;
    const u64 bp0 = pack2(b[c0], b[c0 + 1]), bp1 = pack2(b[c0 + 2], b[c0 + 3]);
    __syncthreads();

    const int ntiles = (N_NODES + 63) / 64;
    for (int t = blockIdx.x; t < ntiles; t += gridDim.x) {
        const int n0 = t * 64;
        {   // load A tile: 4 threads per row, 8 float4 each
            const int lr = tid >> 2, sub = tid & 3;
            const int n = n0 + lr;
            float4* ap = (float4*)(sA + lr * 128);
            if (n < N_NODES) {
                const float4* xp = (const float4*)(x + (size_t)n * 128);
                #pragma unroll
                for (int i = 0; i < 8; i++) ap[sub * 8 + i] = xp[sub * 8 + i];
            } else {
                float4 z = make_float4(0.f, 0.f, 0.f, 0.f);
                #pragma unroll
                for (int i = 0; i < 8; i++) ap[sub * 8 + i] = z;
            }
        }
        __syncthreads();
        u64 acc[8][2];
        #pragma unroll
        for (int r = 0; r < 8; r++) { acc[r][0] = bp0; acc[r][1] = bp1; }
        for (int k = 0; k < 128; k += 4) {
            float4 a4[8];
            #pragma unroll
            for (int r = 0; r < 8; r++)
                a4[r] = *(const float4*)(sA + (r0 + r) * 128 + k);
            #pragma unroll
            for (int kk = 0; kk < 4; kk++) {
                const ulonglong2 bv = *(const ulonglong2*)(sW + (k + kk) * 128 + c0);
                #pragma unroll
                for (int r = 0; r < 8; r++) {
                    const float a = ((const float*)&a4[r])[kk];
                    const u64 p = pack2(a, a);
                    fma2(acc[r][0], p, bv.x); fma2(acc[r][1], p, bv.y);
                }
            }
        }
        #pragma unroll
        for (int r = 0; r < 8; r++) {
            const int n = n0 + r0 + r;
            if (n < N_NODES) {
                float2 x0 = unpack2(acc[r][0]), x1 = unpack2(acc[r][1]);
                *(float4*)(g_h + (size_t)n * 128 + c0) =
                    make_float4(fmaxf(x0.x, 0.f), fmaxf(x0.y, 0.f),
                                fmaxf(x1.x, 0.f), fmaxf(x1.y, 0.f));
            }
        }
        __syncthreads();
    }
}

// ============================================================================
// fused edge message kernel:
//   m = relu([h[src], e_attr] @ W1 + b1) @ W2 + b2 ; atomicAdd into agg[dst]
// 256 threads = 8 warps; tile = 64 edges; warp: 8 rows x 128 cols.
// W1 [144][128] + W2 [128][128] resident in SMEM.
// ============================================================================
__global__ __launch_bounds__(256, 1) void edge_msg_kernel(
    const int* __restrict__ src, const int* __restrict__ dst,
    const float* __restrict__ edge_attr,
    const float* __restrict__ W1, const float* __restrict__ b1,
    const float* __restrict__ W2, const float* __restrict__ b2)
{
    extern __shared__ float sm[];
    float* sW1 = sm;               // [144][128]
    float* sW2 = sW1 + 144 * 128;  // [128][128]
    float* sA  = sW2 + 128 * 128;  // [64][144]
    float* sH  = sA + 64 * 144;    // [64][128]
    const int tid = threadIdx.x;
    for (int i = tid; i < 144 * 128; i += 256) sW1[i] = W1[i];
    for (int i = tid; i < 128 * 128; i += 256) sW2[i] = W2[i];
    const int warp = tid >> 5, lane = tid & 31;
    const int r0 = warp * 8, c0 = lane * 4;
    const u64 b1p0 = pack2(b1[c0], b1[c0 + 1]), b1p1 = pack2(b1[c0 + 2], b1[c0 + 3]);
    const u64 b2p0 = pack2(b2[c0], b2[c0 + 1]), b2p1 = pack2(b2[c0 + 2], b2[c0 + 3]);
    __syncthreads();

    const int ntiles = N_EDGES / 64;   // 12500 exact
    for (int t = blockIdx.x; t < ntiles; t += gridDim.x) {
        const int e0 = t * 64;
        {   // gather inputs: 4 threads per edge
            const int le = tid >> 2, sub = tid & 3;
            const int e = e0 + le;
            const int s = src[e];
            const float4* hp = (const float4*)(g_h + (size_t)s * 128);
            float4* ap = (float4*)(sA + le * 144);
            #pragma unroll
            for (int i = 0; i < 8; i++) ap[sub * 8 + i] = hp[sub * 8 + i];
            // edge_attr: 4 floats each -> columns 128..143
            *(float4*)(sA + le * 144 + 128 + sub * 4) =
                *(const float4*)(edge_attr + (size_t)e * 16 + sub * 4);
        }
        __syncthreads();

        // GEMM1: hid = relu(A[64,144] @ W1 + b1)
        u64 acc[8][2];
        #pragma unroll
        for (int r = 0; r < 8; r++) { acc[r][0] = b1p0; acc[r][1] = b1p1; }
        for (int k = 0; k < 144; k += 4) {
            float4 a4[8];
            #pragma unroll
            for (int r = 0; r < 8; r++)
                a4[r] = *(const float4*)(sA + (r0 + r) * 144 + k);
            #pragma unroll
            for (int kk = 0; kk < 4; kk++) {
                const ulonglong2 bv = *(const ulonglong2*)(sW1 + (k + kk) * 128 + c0);
                #pragma unroll
                for (int r = 0; r < 8; r++) {
                    const float a = ((const float*)&a4[r])[kk];
                    const u64 p = pack2(a, a);
                    fma2(acc[r][0], p, bv.x); fma2(acc[r][1], p, bv.y);
                }
            }
        }
        #pragma unroll
        for (int r = 0; r < 8; r++) {
            float2 x0 = unpack2(acc[r][0]), x1 = unpack2(acc[r][1]);
            *(float4*)(sH + (r0 + r) * 128 + c0) =
                make_float4(fmaxf(x0.x, 0.f), fmaxf(x0.y, 0.f),
                            fmaxf(x1.x, 0.f), fmaxf(x1.y, 0.f));
        }
        __syncthreads();

        // GEMM2: m = hid[64,128] @ W2 + b2
        #pragma unroll
        for (int r = 0; r < 8; r++) { acc[r][0] = b2p0; acc[r][1] = b2p1; }
        for (int k = 0; k < 128; k += 4) {
            float4 a4[8];
            #pragma unroll
            for (int r = 0; r < 8; r++)
                a4[r] = *(const float4*)(sH + (r0 + r) * 128 + k);
            #pragma unroll
            for (int kk = 0; kk < 4; kk++) {
                const ulonglong2 bv = *(const ulonglong2*)(sW2 + (k + kk) * 128 + c0);
                #pragma unroll
                for (int r = 0; r < 8; r++) {
                    const float a = ((const float*)&a4[r])[kk];
                    const u64 p = pack2(a, a);
                    fma2(acc[r][0], p, bv.x); fma2(acc[r][1], p, bv.y);
                }
            }
        }
        // scatter-add to agg[dst]
        #pragma unroll
        for (int r = 0; r < 8; r++) {
            const int e = e0 + r0 + r;
            const int d = dst[e];
            float* o = g_agg + (size_t)d * 128 + c0;
            float2 x0 = unpack2(acc[r][0]), x1 = unpack2(acc[r][1]);
            atomicAdd(o + 0, x0.x);
            atomicAdd(o + 1, x0.y);
            atomicAdd(o + 2, x1.x);
            atomicAdd(o + 3, x1.y);
        }
        __syncthreads();
    }
}

// ============================================================================
// GRU gemms: gi = agg @ wih^T + bih ; gh = h @ whh^T + bhh
// grid.y in [0,6): which = y/3 (0:gi, 1:gh), gate = y%3.
// 256 threads = 8 warps; 64-node tiles; warp: 8 rows x 128 cols.
// ============================================================================
__global__ __launch_bounds__(256, 2) void gru_gemm_kernel(
    const float* __restrict__ wih, const float* __restrict__ whh,
    const float* __restrict__ bih, const float* __restrict__ bhh)
{
    extern __shared__ float sm[];
    float* sW = sm;              // [128][132] transposed chunk
    float* sA = sW + 128 * 132;  // [64][128]
    const int which = blockIdx.y / 3;
    const int gate  = blockIdx.y % 3;
    const float* W    = (which ? whh : wih) + (size_t)gate * 128 * 128;
    const float* bias = (which ? bhh : bih) + gate * 128;
    const float* A    = which ? g_h : g_agg;
    float* out        = which ? g_gh : g_gi;

    const int tid = threadIdx.x;
    for (int i = tid; i < 128 * 128; i += 256) {
        int j = i >> 7, k = i & 127;
        sW[k * 132 + j] = W[i];     // W[j*128+k] -> sW[k][j]
    }
    const int warp = tid >> 5, lane = tid & 31;
    const int r0 = warp * 8, c0 = lane * 4;
    const u64 bp0 = pack2(bias[c0], bias[c0 + 1]), bp1 = pack2(bias[c0 + 2], bias[c0 + 3]);
    __syncthreads();

    const int ntiles = (N_NODES + 63) / 64;
    for (int t = blockIdx.x; t < ntiles; t += gridDim.x) {
        const int n0 = t * 64;
        {
            const int lr = tid >> 2, sub = tid & 3;
            const int n = n0 + lr;
            float4* ap = (float4*)(sA + lr * 128);
            if (n < N_NODES) {
                const float4* xp = (const float4*)(A + (size_t)n * 128);
                #pragma unroll
                for (int i = 0; i < 8; i++) ap[sub * 8 + i] = xp[sub * 8 + i];
            } else {
                float4 z = make_float4(0.f, 0.f, 0.f, 0.f);
                #pragma unroll
                for (int i = 0; i < 8; i++) ap[sub * 8 + i] = z;
            }
        }
        __syncthreads();
        u64 acc[8][2];
        #pragma unroll
        for (int r = 0; r < 8; r++) { acc[r][0] = bp0; acc[r][1] = bp1; }
        for (int k = 0; k < 128; k += 4) {
            float4 a4[8];
            #pragma unroll
            for (int r = 0; r < 8; r++)
                a4[r] = *(const float4*)(sA + (r0 + r) * 128 + k);
            #pragma unroll
            for (int kk = 0; kk < 4; kk++) {
                const ulonglong2 bv = *(const ulonglong2*)(sW + (k + kk) * 132 + c0);
                #pragma unroll
                for (int r = 0; r < 8; r++) {
                    const float a = ((const float*)&a4[r])[kk];
                    const u64 p = pack2(a, a);
                    fma2(acc[r][0], p, bv.x); fma2(acc[r][1], p, bv.y);
                }
            }
        }
        #pragma unroll
        for (int r = 0; r < 8; r++) {
            const int n = n0 + r0 + r;
            if (n < N_NODES) {
                float2 x0 = unpack2(acc[r][0]), x1 = unpack2(acc[r][1]);
                *(float4*)(out + (size_t)n * 384 + gate * 128 + c0) =
                    make_float4(x0.x, x0.y, x1.x, x1.y);
            }
        }
        __syncthreads();
    }
}

// ============================================================================
// fused GRU gates + BatchNorm + residual
// ============================================================================
__global__ void gru_gate_kernel(
    const float* __restrict__ gamma, const float* __restrict__ beta,
    const float* __restrict__ mean, const float* __restrict__ var)
{
    const int idx = blockIdx.x * blockDim.x + threadIdx.x;
    if (idx >= N_NODES * HIDDEN) return;
    const int c = idx & 127;
    const size_t n = (size_t)(idx >> 7);
    const float* gi = g_gi + n * 384;
    const float* gh = g_gh + n * 384;
    const float hv = g_h[idx];
    const float r = 1.f / (1.f + expf(-(gi[c] + gh[c])));
    const float z = 1.f / (1.f + expf(-(gi[128 + c] + gh[128 + c])));
    const float nn = tanhf(gi[256 + c] + r * gh[256 + c]);
    const float hnew = (1.f - z) * nn + z * hv;
    const float bn = (hnew - mean[c]) * rsqrtf(var[c] + 1e-5f) * gamma[c] + beta[c];
    g_h[idx] = hv + bn;
}

// ---------------- aux kernels ----------------
__global__ void zero_agg_kernel() {
    const int idx = blockIdx.x * blockDim.x + threadIdx.x;
    if (idx < N_NODES * HIDDEN / 4)
        ((float4*)g_agg)[idx] = make_float4(0.f, 0.f, 0.f, 0.f);
}

__global__ void init_readout_kernel() {
    const int idx = blockIdx.x * blockDim.x + threadIdx.x;
    if (idx < N_GRAPHS * HIDDEN) { g_zsum[idx] = 0.f; g_zmax[idx] = 0x00800000u; }
    if (idx < N_GRAPHS) g_cnt[idx] = 0.f;
}

__global__ void seg_reduce_kernel(const int* __restrict__ batch) {
    const int gid = blockIdx.x * blockDim.x + threadIdx.x;   // N_NODES*32
    if (gid >= N_NODES * 32) return;
    const int n = gid >> 5, q = gid & 31;
    const int g = batch[n];
    const float4 hv = *(const float4*)(g_h + (size_t)n * 128 + q * 4);
    float* zs = g_zsum + g * 128 + q * 4;
    atomicAdd(zs + 0, hv.x); atomicAdd(zs + 1, hv.y);
    atomicAdd(zs + 2, hv.z); atomicAdd(zs + 3, hv.w);
    unsigned* zm = g_zmax + g * 128 + q * 4;
    atomicMax(zm + 0, fenc(hv.x)); atomicMax(zm + 1, fenc(hv.y));
    atomicMax(zm + 2, fenc(hv.z)); atomicMax(zm + 3, fenc(hv.w));
    if (q == 0) atomicAdd(g_cnt + g, 1.f);
}

__global__ void readout_kernel(const float* __restrict__ ro_w,
                               const float* __restrict__ ro_b,
                               float* __restrict__ out)
{
    __shared__ float sbuf[256];
    const int g = blockIdx.x, j = threadIdx.x;   // 128 threads
    const float c = g_cnt[g];
    const float inv = 1.f / fmaxf(c, 1.f);
    sbuf[j]       = g_zsum[g * 128 + j] * inv;
    sbuf[128 + j] = (c > 0.f) ? fdec(g_zmax[g * 128 + j]) : 0.f;
    __syncthreads();
    float acc = ro_b[j];
    #pragma unroll 8
    for (int k = 0; k < 256; k++) acc = fmaf(sbuf[k], ro_w[k * 128 + j], acc);
    out[g * 128 + j] = fmaxf(acc, 0.f);
}

// ============================================================================
extern "C" void kernel_launch(void* const* d_in, const int* in_sizes, int n_in,
                              void* d_out, int out_size)
{
    // setup_inputs order; n_graphs (scalar) may or may not appear as input 4
    const int shift = (in_sizes[4] == 1) ? 1 : 0;
    const float* x         = (const float*)d_in[0];
    const int*   edge_idx  = (const int*)  d_in[1];
    const float* edge_attr = (const float*)d_in[2];
    const int*   batch     = (const int*)  d_in[3];
    const float* lin_in_w  = (const float*)d_in[4 + shift];
    const float* lin_in_b  = (const float*)d_in[5 + shift];
    const float* msg_w1    = (const float*)d_in[6 + shift];
    const float* msg_b1    = (const float*)d_in[7 + shift];
    const float* msg_w2    = (const float*)d_in[8 + shift];
    const float* msg_b2    = (const float*)d_in[9 + shift];
    const float* bn_gamma  = (const float*)d_in[10 + shift];
    const float* bn_beta   = (const float*)d_in[11 + shift];
    const float* bn_mean   = (const float*)d_in[12 + shift];
    const float* bn_var    = (const float*)d_in[13 + shift];
    const float* gru_wih   = (const float*)d_in[14 + shift];
    const float* gru_whh   = (const float*)d_in[15 + shift];
    const float* gru_bih   = (const float*)d_in[16 + shift];
    const float* gru_bhh   = (const float*)d_in[17 + shift];
    const float* ro_w      = (const float*)d_in[18 + shift];
    const float* ro_b      = (const float*)d_in[19 + shift];
    float* out = (float*)d_out;

    static bool inited = false;
    if (!inited) {
        cudaFuncSetAttribute(edge_msg_kernel, cudaFuncAttributeMaxDynamicSharedMemorySize, EDGE_SMEM);
        cudaFuncSetAttribute(lin_in_kernel,   cudaFuncAttributeMaxDynamicSharedMemorySize, LIN_SMEM);
        cudaFuncSetAttribute(gru_gemm_kernel, cudaFuncAttributeMaxDynamicSharedMemorySize, GRU_SMEM);
        inited = true;
    }

    const int* src = edge_idx;
    const int* dst = edge_idx + N_EDGES;

    lin_in_kernel<<<296, 256, LIN_SMEM>>>(x, lin_in_w, lin_in_b);

    for (int l = 0; l < N_LAYERS; l++) {
        zero_agg_kernel<<<(N_NODES * HIDDEN / 4 + 255) / 256, 256>>>();
        edge_msg_kernel<<<148, 256, EDGE_SMEM>>>(
            src, dst, edge_attr,
            msg_w1 + (size_t)l * 144 * 128, msg_b1 + l * 128,
            msg_w2 + (size_t)l * 128 * 128, msg_b2 + l * 128);
        gru_gemm_kernel<<<dim3(296, 6), 256, GRU_SMEM>>>(
            gru_wih + (size_t)l * 384 * 128, gru_whh + (size_t)l * 384 * 128,
            gru_bih + l * 384, gru_bhh + l * 384);
        gru_gate_kernel<<<(N_NODES * HIDDEN + 255) / 256, 256>>>(
            bn_gamma + l * 128, bn_beta + l * 128, bn_mean + l * 128, bn_var + l * 128);
    }

    init_readout_kernel<<<(N_GRAPHS * HIDDEN + 255) / 256, 256>>>();
    seg_reduce_kernel<<<(N_NODES * 32 + 255) / 256, 256>>>(batch);
    readout_kernel<<<N_GRAPHS, 128>>>(ro_w, ro_b, out);
}

// round 9
// speedup vs baseline: 2.0016x; 1.9549x over previous
#include <cuda_runtime.h>
#include <cuda_bf16.h>
#include <cstdint>
#include <math.h>

#define N_NODES 50000
#define N_EDGES 800000
#define IN_DIM 128
#define EDGE_DIM 16
#define HIDDEN 128
#define N_LAYERS 3
#define N_GRAPHS 256

typedef unsigned int uint;

// ---------------- scratch (device globals: allocation-free) ----------------
__device__ float g_h[(size_t)N_NODES * HIDDEN];
__device__ float g_agg[(size_t)N_NODES * HIDDEN];
__device__ float g_gi[(size_t)N_NODES * 3 * HIDDEN];
__device__ float g_gh[(size_t)N_NODES * 3 * HIDDEN];
__device__ float g_zsum[N_GRAPHS * HIDDEN];
__device__ unsigned g_zmax[N_GRAPHS * HIDDEN];
__device__ float g_cnt[N_GRAPHS];

// bf16 split weight staging: [K][128] row-major per matrix
#define OFF_LIN 0
#define OFF_M1  16384
#define OFF_M2  71680
#define OFF_WIH 120832
#define OFF_WHH 268288
#define W_TOTAL 415744
__device__ __nv_bfloat16 g_wh[W_TOTAL];
__device__ __nv_bfloat16 g_wl[W_TOTAL];

// ---------------- misc helpers ----------------
__device__ __forceinline__ unsigned fenc(float f) {
    unsigned u = __float_as_uint(f);
    return (u & 0x80000000u) ? ~u : (u | 0x80000000u);
}
__device__ __forceinline__ float fdec(unsigned u) {
    return __uint_as_float((u & 0x80000000u) ? (u ^ 0x80000000u) : ~u);
}

// split two fp32 into packed bf16 hi-word and lo-word (residual)
__device__ __forceinline__ void split2p(float a, float b, uint& h, uint& l) {
    __nv_bfloat162 t = __floats2bfloat162_rn(a, b);   // x=a (low), y=b (high)
    h = *reinterpret_cast<uint*>(&t);
    float ah = __uint_as_float(h << 16);
    float bh = __uint_as_float(h & 0xffff0000u);
    __nv_bfloat162 t2 = __floats2bfloat162_rn(a - ah, b - bh);
    l = *reinterpret_cast<uint*>(&t2);
}
__device__ __forceinline__ void split_f4(float4 f, uint2& H, uint2& L) {
    split2p(f.x, f.y, H.x, L.x);
    split2p(f.z, f.w, H.y, L.y);
}

// ---------------- mma / ldmatrix primitives (sm_80-level PTX) ----------------
__device__ __forceinline__ uint32_t sm_addr(const void* p) {
    return (uint32_t)__cvta_generic_to_shared(p);
}
__device__ __forceinline__ void ldsm4(uint* r, uint32_t a) {
    asm volatile("ldmatrix.sync.aligned.m8n8.x4.shared.b16 {%0,%1,%2,%3},[%4];"
        : "=r"(r[0]), "=r"(r[1]), "=r"(r[2]), "=r"(r[3]) : "r"(a));
}
__device__ __forceinline__ void ldsm4t(uint* r, uint32_t a) {
    asm volatile("ldmatrix.sync.aligned.m8n8.x4.trans.shared.b16 {%0,%1,%2,%3},[%4];"
        : "=r"(r[0]), "=r"(r[1]), "=r"(r[2]), "=r"(r[3]) : "r"(a));
}
__device__ __forceinline__ void mmabf16(float* d, const uint* a, const uint* b) {
    asm volatile("mma.sync.aligned.m16n8k16.row.col.f32.bf16.bf16.f32 "
        "{%0,%1,%2,%3},{%4,%5,%6,%7},{%8,%9},{%0,%1,%2,%3};"
        : "+f"(d[0]), "+f"(d[1]), "+f"(d[2]), "+f"(d[3])
        : "r"(a[0]), "r"(a[1]), "r"(a[2]), "r"(a[3]), "r"(b[0]), "r"(b[1]));
}

// warp-level GEMM fragment: 2 m16-tiles x NT n8-tiles, NK16 k-steps.
// A in smem (row-major bf16, stride ASTR bytes); B in smem [K][128] bf16,
// stride 272 bytes (136 elems). acc layout [2*NT][4].
template<int NK16, int NT, int ASTR>
__device__ __forceinline__ void wgemm(float* acc, uint32_t Ab, uint32_t Bb,
                                      uint32_t aOff, uint32_t bOff) {
    #pragma unroll
    for (int k = 0; k < NK16; k++) {
        uint a[2][4];
        ldsm4(a[0], Ab + aOff + k * 32);
        ldsm4(a[1], Ab + aOff + k * 32 + 16 * ASTR);
        uint bb[NT][2];
        #pragma unroll
        for (int p2 = 0; p2 < NT / 2; p2++) {
            uint r[4];
            ldsm4t(r, Bb + bOff + k * 16 * 272 + p2 * 32);
            bb[2*p2][0] = r[0]; bb[2*p2][1] = r[1];
            bb[2*p2+1][0] = r[2]; bb[2*p2+1][1] = r[3];
        }
        #pragma unroll
        for (int mt = 0; mt < 2; mt++)
            #pragma unroll
            for (int nt = 0; nt < NT; nt++)
                mmabf16(acc + (mt * NT + nt) * 4, a[mt], bb[nt]);
    }
}

// ============================================================================
// weight conversion: fp32 -> canonical [K][128] bf16 hi/lo staging
// seg: 0=lin, 1=msg_w1(3 layers), 2=msg_w2, 3=gru_wih(transposed), 4=gru_whh
// ============================================================================
__global__ void conv_w_kernel(const float* __restrict__ lin_w,
                              const float* __restrict__ m1,
                              const float* __restrict__ m2,
                              const float* __restrict__ wih,
                              const float* __restrict__ whh)
{
    const int i = blockIdx.x * 256 + threadIdx.x;
    const int seg = blockIdx.y;
    int sz, off; float v;
    switch (seg) {
    case 0: sz = 16384;  off = OFF_LIN; if (i >= sz) return; v = lin_w[i]; break;
    case 1: sz = 55296;  off = OFF_M1;  if (i >= sz) return; v = m1[i]; break;
    case 2: sz = 49152;  off = OFF_M2;  if (i >= sz) return; v = m2[i]; break;
    default: {
        sz = 147456; off = (seg == 3) ? OFF_WIH : OFF_WHH;
        if (i >= sz) return;
        const float* W = (seg == 3) ? wih : whh;
        const int m = i >> 14, t = i & 16383, k = t >> 7, j = t & 127;
        v = W[(m / 3) * 49152 + ((m % 3) * 128 + j) * 128 + k];
        break;
    }}
    __nv_bfloat16 h = __float2bfloat16(v);
    float r = v - __bfloat162float(h);
    g_wh[off + i] = h;
    g_wl[off + i] = __float2bfloat16(r);
}

// ============================================================================
// edge message kernel (mma): 128-edge tiles, 256 thr = 8 warps (warp: 32x64)
//   GEMM1: [128 x 144] @ W1 -> relu(+b1) -> re-split -> GEMM2 @ W2 -> +b2
//   -> atomicAdd into g_agg[dst]
// ============================================================================
#define E_AW  304      // A stride bytes (152 bf16)
#define S_W1H 0
#define S_W1L 39168
#define S_W2H 78336
#define S_W2L 113152
#define S_AH  147968
#define S_AL  186880
#define S_B1  225792
#define S_B2  226304
#define S_DST 226816
#define EDGE_SMEM 227328

__global__ __launch_bounds__(256, 1) void edge_mma_kernel(
    const int* __restrict__ src, const int* __restrict__ dst,
    const float* __restrict__ edge_attr, int l,
    const float* __restrict__ b1, const float* __restrict__ b2)
{
    extern __shared__ char sm[];
    const int tid = threadIdx.x;
    const int wid = tid >> 5, lane = tid & 31;
    const uint32_t base = sm_addr(sm);

    // ---- copy split weights to smem (padded stride 136 elems) ----
    {
        const uint* w1h = (const uint*)(g_wh + OFF_M1 + (size_t)l * 18432);
        const uint* w1l = (const uint*)(g_wl + OFF_M1 + (size_t)l * 18432);
        for (int i = tid; i < 144 * 64; i += 256) {
            const int k = i >> 6, n2 = i & 63;
            ((uint*)(sm + S_W1H))[k * 68 + n2] = w1h[i];
            ((uint*)(sm + S_W1L))[k * 68 + n2] = w1l[i];
        }
        const uint* w2h = (const uint*)(g_wh + OFF_M2 + (size_t)l * 16384);
        const uint* w2l = (const uint*)(g_wl + OFF_M2 + (size_t)l * 16384);
        for (int i = tid; i < 128 * 64; i += 256) {
            const int k = i >> 6, n2 = i & 63;
            ((uint*)(sm + S_W2H))[k * 68 + n2] = w2h[i];
            ((uint*)(sm + S_W2L))[k * 68 + n2] = w2l[i];
        }
        if (tid < 128) {
            ((float*)(sm + S_B1))[tid] = b1[tid];
            ((float*)(sm + S_B2))[tid] = b2[tid];
        }
    }
    __syncthreads();

    const float* sb1 = (const float*)(sm + S_B1);
    const float* sb2 = (const float*)(sm + S_B2);
    int* sDst = (int*)(sm + S_DST);
    const int m0 = (wid & 3) * 32, n0 = (wid >> 2) * 64;
    const uint32_t aOff = (uint32_t)(m0 + (lane & 15)) * E_AW + (lane >> 4) * 16;
    const uint32_t bOff = (uint32_t)(lane & 15) * 272 + n0 * 2 + (lane >> 4) * 16;
    const uint32_t aH = base + S_AH, aL = base + S_AL;
    const uint32_t w1H = base + S_W1H, w1L = base + S_W1L;
    const uint32_t w2H = base + S_W2H, w2L = base + S_W2L;

    const int ntiles = N_EDGES / 128;    // 6250
    for (int t = blockIdx.x; t < ntiles; t += gridDim.x) {
        const int e0 = t * 128;
        // ---- gather: h[src] + edge_attr -> bf16 hi/lo tiles ----
        {
            const int row = tid >> 1, half = tid & 1;
            const int e = e0 + row;
            if (tid < 128) sDst[tid] = dst[e0 + tid];
            const int s = src[e];
            const float4* hp = (const float4*)(g_h + (size_t)s * 128) + half * 16;
            const uint b0 = (uint)row * E_AW + half * 128;
            #pragma unroll
            for (int i = 0; i < 16; i++) {
                uint2 H, L; split_f4(hp[i], H, L);
                *(uint2*)(sm + S_AH + b0 + i * 8) = H;
                *(uint2*)(sm + S_AL + b0 + i * 8) = L;
            }
            if (!half) {
                const float4* ep = (const float4*)(edge_attr + (size_t)e * 16);
                #pragma unroll
                for (int i = 0; i < 4; i++) {
                    uint2 H, L; split_f4(ep[i], H, L);
                    *(uint2*)(sm + S_AH + (uint)row * E_AW + 256 + i * 8) = H;
                    *(uint2*)(sm + S_AL + (uint)row * E_AW + 256 + i * 8) = L;
                }
            }
        }
        __syncthreads();

        // ---- GEMM1 (K=144, 3-pass split) ----
        float acc[16][4];
        #pragma unroll
        for (int i = 0; i < 16; i++) { acc[i][0]=0; acc[i][1]=0; acc[i][2]=0; acc[i][3]=0; }
        #pragma unroll 1
        for (int p = 0; p < 3; p++)
            wgemm<9, 8, E_AW>(&acc[0][0], (p == 2) ? aL : aH,
                              (p == 1) ? w1L : w1H, aOff, bOff);
        __syncthreads();   // all warps done reading A before overwrite

        // ---- epilogue1: relu(+b1) -> re-split into A buffers ----
        #pragma unroll
        for (int mt = 0; mt < 2; mt++)
            #pragma unroll
            for (int nt = 0; nt < 8; nt++) {
                float* a4 = acc[mt * 8 + nt];
                const int col = n0 + nt * 8 + 2 * (lane & 3);
                const int r0 = m0 + mt * 16 + (lane >> 2);
                float v0 = fmaxf(a4[0] + sb1[col], 0.f), v1 = fmaxf(a4[1] + sb1[col+1], 0.f);
                float v2 = fmaxf(a4[2] + sb1[col], 0.f), v3 = fmaxf(a4[3] + sb1[col+1], 0.f);
                uint h, lo;
                split2p(v0, v1, h, lo);
                *(uint*)(sm + S_AH + (uint)r0 * E_AW + col * 2) = h;
                *(uint*)(sm + S_AL + (uint)r0 * E_AW + col * 2) = lo;
                split2p(v2, v3, h, lo);
                *(uint*)(sm + S_AH + (uint)(r0 + 8) * E_AW + col * 2) = h;
                *(uint*)(sm + S_AL + (uint)(r0 + 8) * E_AW + col * 2) = lo;
            }
        __syncthreads();

        // ---- GEMM2 (K=128, 3-pass split) ----
        #pragma unroll
        for (int i = 0; i < 16; i++) { acc[i][0]=0; acc[i][1]=0; acc[i][2]=0; acc[i][3]=0; }
        #pragma unroll 1
        for (int p = 0; p < 3; p++)
            wgemm<8, 8, E_AW>(&acc[0][0], (p == 2) ? aL : aH,
                              (p == 1) ? w2L : w2H, aOff, bOff);

        // ---- epilogue2: +b2, scatter-add ----
        #pragma unroll
        for (int mt = 0; mt < 2; mt++)
            #pragma unroll
            for (int nt = 0; nt < 8; nt++) {
                float* a4 = acc[mt * 8 + nt];
                const int col = n0 + nt * 8 + 2 * (lane & 3);
                const int r0 = m0 + mt * 16 + (lane >> 2);
                const int d0 = sDst[r0], d1 = sDst[r0 + 8];
                atomicAdd(g_agg + (size_t)d0 * 128 + col,     a4[0] + sb2[col]);
                atomicAdd(g_agg + (size_t)d0 * 128 + col + 1, a4[1] + sb2[col + 1]);
                atomicAdd(g_agg + (size_t)d1 * 128 + col,     a4[2] + sb2[col]);
                atomicAdd(g_agg + (size_t)d1 * 128 + col + 1, a4[3] + sb2[col + 1]);
            }
        __syncthreads();   // before next tile's gather overwrites A
    }
}

// ============================================================================
// node GEMM body (mma): out[n,128] = act(A[n,128] @ W + b); 64-row tiles,
// 256 thr = 8 warps (warp 32x32), 2 CTAs/SM.
// ============================================================================
#define N_AW 272                 // A stride bytes (136 bf16)
#define NS_WH 0
#define NS_WL 34816
#define NS_AH 69632
#define NS_AL 87040
#define NS_B  104448
#define NODE_SMEM 104960

__device__ __forceinline__ void node_body(
    const float* __restrict__ A, float* __restrict__ out, int ostride,
    const uint* __restrict__ WhU, const uint* __restrict__ WlU,
    const float* __restrict__ bias, int relu)
{
    extern __shared__ char sm[];
    const int tid = threadIdx.x;
    const int wid = tid >> 5, lane = tid & 31;
    const uint32_t base = sm_addr(sm);

    for (int i = tid; i < 128 * 64; i += 256) {
        const int k = i >> 6, n2 = i & 63;
        ((uint*)(sm + NS_WH))[k * 68 + n2] = WhU[i];
        ((uint*)(sm + NS_WL))[k * 68 + n2] = WlU[i];
    }
    if (tid < 128) ((float*)(sm + NS_B))[tid] = bias[tid];
    __syncthreads();

    const float* sb = (const float*)(sm + NS_B);
    const int m0 = (wid & 1) * 32, n0 = (wid >> 1) * 32;
    const uint32_t aOff = (uint32_t)(m0 + (lane & 15)) * N_AW + (lane >> 4) * 16;
    const uint32_t bOff = (uint32_t)(lane & 15) * 272 + n0 * 2 + (lane >> 4) * 16;
    const uint32_t aH = base + NS_AH, aL = base + NS_AL;
    const uint32_t wH = base + NS_WH, wL = base + NS_WL;

    const int ntiles = (N_NODES + 63) / 64;  // 782
    for (int t = blockIdx.x; t < ntiles; t += gridDim.x) {
        const int r0g = t * 64;
        {   // load + split A rows
            const int trow = tid >> 2, q = tid & 3;
            const int rg = r0g + trow;
            const uint b0 = (uint)trow * N_AW + q * 64;
            if (rg < N_NODES) {
                const float4* hp = (const float4*)(A + (size_t)rg * 128) + q * 8;
                #pragma unroll
                for (int i = 0; i < 8; i++) {
                    uint2 H, L; split_f4(hp[i], H, L);
                    *(uint2*)(sm + NS_AH + b0 + i * 8) = H;
                    *(uint2*)(sm + NS_AL + b0 + i * 8) = L;
                }
            } else {
                const uint2 z = make_uint2(0u, 0u);
                #pragma unroll
                for (int i = 0; i < 8; i++) {
                    *(uint2*)(sm + NS_AH + b0 + i * 8) = z;
                    *(uint2*)(sm + NS_AL + b0 + i * 8) = z;
                }
            }
        }
        __syncthreads();

        float acc[8][4];
        #pragma unroll
        for (int i = 0; i < 8; i++) { acc[i][0]=0; acc[i][1]=0; acc[i][2]=0; acc[i][3]=0; }
        #pragma unroll 1
        for (int p = 0; p < 3; p++)
            wgemm<8, 4, N_AW>(&acc[0][0], (p == 2) ? aL : aH,
                              (p == 1) ? wL : wH, aOff, bOff);
        __syncthreads();   // A reads done before next tile store

        #pragma unroll
        for (int mt = 0; mt < 2; mt++)
            #pragma unroll
            for (int nt = 0; nt < 4; nt++) {
                float* a4 = acc[mt * 4 + nt];
                const int col = n0 + nt * 8 + 2 * (lane & 3);
                const int r = m0 + mt * 16 + (lane >> 2);
                const int rg0 = r0g + r, rg1 = rg0 + 8;
                float v0 = a4[0] + sb[col], v1 = a4[1] + sb[col + 1];
                float v2 = a4[2] + sb[col], v3 = a4[3] + sb[col + 1];
                if (relu) {
                    v0 = fmaxf(v0, 0.f); v1 = fmaxf(v1, 0.f);
                    v2 = fmaxf(v2, 0.f); v3 = fmaxf(v3, 0.f);
                }
                if (rg0 < N_NODES)
                    *(float2*)(out + (size_t)rg0 * ostride + col) = make_float2(v0, v1);
                if (rg1 < N_NODES)
                    *(float2*)(out + (size_t)rg1 * ostride + col) = make_float2(v2, v3);
            }
    }
}

__global__ __launch_bounds__(256, 2) void lin_mma_kernel(
    const float* __restrict__ x, const float* __restrict__ b)
{
    node_body(x, g_h, 128, (const uint*)(g_wh + OFF_LIN),
              (const uint*)(g_wl + OFF_LIN), b, 1);
}

__global__ __launch_bounds__(256, 2) void gru_mma_kernel(
    int l, const float* __restrict__ bih, const float* __restrict__ bhh)
{
    const int which = blockIdx.y / 3, gate = blockIdx.y % 3;
    const float* A = which ? g_h : g_agg;
    float* out = (which ? g_gh : g_gi) + gate * 128;
    const size_t wOff = (size_t)(which ? OFF_WHH : OFF_WIH) + (size_t)(l * 3 + gate) * 16384;
    const float* bias = (which ? bhh : bih) + gate * 128;
    node_body(A, out, 384, (const uint*)(g_wh + wOff), (const uint*)(g_wl + wOff), bias, 0);
}

// ============================================================================
// fused GRU gates + BatchNorm + residual
// ============================================================================
__global__ void gru_gate_kernel(
    const float* __restrict__ gamma, const float* __restrict__ beta,
    const float* __restrict__ mean, const float* __restrict__ var)
{
    const int idx = blockIdx.x * blockDim.x + threadIdx.x;
    if (idx >= N_NODES * HIDDEN) return;
    const int c = idx & 127;
    const size_t n = (size_t)(idx >> 7);
    const float* gi = g_gi + n * 384;
    const float* gh = g_gh + n * 384;
    const float hv = g_h[idx];
    const float r = 1.f / (1.f + expf(-(gi[c] + gh[c])));
    const float z = 1.f / (1.f + expf(-(gi[128 + c] + gh[128 + c])));
    const float nn = tanhf(gi[256 + c] + r * gh[256 + c]);
    const float hnew = (1.f - z) * nn + z * hv;
    const float bn = (hnew - mean[c]) * rsqrtf(var[c] + 1e-5f) * gamma[c] + beta[c];
    g_h[idx] = hv + bn;
}

// ---------------- aux kernels ----------------
__global__ void zero_agg_kernel() {
    const int idx = blockIdx.x * blockDim.x + threadIdx.x;
    if (idx < N_NODES * HIDDEN / 4)
        ((float4*)g_agg)[idx] = make_float4(0.f, 0.f, 0.f, 0.f);
}

__global__ void init_readout_kernel() {
    const int idx = blockIdx.x * blockDim.x + threadIdx.x;
    if (idx < N_GRAPHS * HIDDEN) { g_zsum[idx] = 0.f; g_zmax[idx] = 0x00800000u; }
    if (idx < N_GRAPHS) g_cnt[idx] = 0.f;
}

__global__ void seg_reduce_kernel(const int* __restrict__ batch) {
    const int gid = blockIdx.x * blockDim.x + threadIdx.x;   // N_NODES*32
    if (gid >= N_NODES * 32) return;
    const int n = gid >> 5, q = gid & 31;
    const int g = batch[n];
    const float4 hv = *(const float4*)(g_h + (size_t)n * 128 + q * 4);
    float* zs = g_zsum + g * 128 + q * 4;
    atomicAdd(zs + 0, hv.x); atomicAdd(zs + 1, hv.y);
    atomicAdd(zs + 2, hv.z); atomicAdd(zs + 3, hv.w);
    unsigned* zm = g_zmax + g * 128 + q * 4;
    atomicMax(zm + 0, fenc(hv.x)); atomicMax(zm + 1, fenc(hv.y));
    atomicMax(zm + 2, fenc(hv.z)); atomicMax(zm + 3, fenc(hv.w));
    if (q == 0) atomicAdd(g_cnt + g, 1.f);
}

__global__ void readout_kernel(const float* __restrict__ ro_w,
                               const float* __restrict__ ro_b,
                               float* __restrict__ out)
{
    __shared__ float sbuf[256];
    const int g = blockIdx.x, j = threadIdx.x;   // 128 threads
    const float c = g_cnt[g];
    const float inv = 1.f / fmaxf(c, 1.f);
    sbuf[j]       = g_zsum[g * 128 + j] * inv;
    sbuf[128 + j] = (c > 0.f) ? fdec(g_zmax[g * 128 + j]) : 0.f;
    __syncthreads();
    float acc = ro_b[j];
    #pragma unroll 8
    for (int k = 0; k < 256; k++) acc = fmaf(sbuf[k], ro_w[k * 128 + j], acc);
    out[g * 128 + j] = fmaxf(acc, 0.f);
}

// ============================================================================
extern "C" void kernel_launch(void* const* d_in, const int* in_sizes, int n_in,
                              void* d_out, int out_size)
{
    const int shift = (in_sizes[4] == 1) ? 1 : 0;
    const float* x         = (const float*)d_in[0];
    const int*   edge_idx  = (const int*)  d_in[1];
    const float* edge_attr = (const float*)d_in[2];
    const int*   batch     = (const int*)  d_in[3];
    const float* lin_in_w  = (const float*)d_in[4 + shift];
    const float* lin_in_b  = (const float*)d_in[5 + shift];
    const float* msg_w1    = (const float*)d_in[6 + shift];
    const float* msg_b1    = (const float*)d_in[7 + shift];
    const float* msg_w2    = (const float*)d_in[8 + shift];
    const float* msg_b2    = (const float*)d_in[9 + shift];
    const float* bn_gamma  = (const float*)d_in[10 + shift];
    const float* bn_beta   = (const float*)d_in[11 + shift];
    const float* bn_mean   = (const float*)d_in[12 + shift];
    const float* bn_var    = (const float*)d_in[13 + shift];
    const float* gru_wih   = (const float*)d_in[14 + shift];
    const float* gru_whh   = (const float*)d_in[15 + shift];
    const float* gru_bih   = (const float*)d_in[16 + shift];
    const float* gru_bhh   = (const float*)d_in[17 + shift];
    const float* ro_w      = (const float*)d_in[18 + shift];
    const float* ro_b      = (const float*)d_in[19 + shift];
    float* out = (float*)d_out;

    static bool inited = false;
    if (!inited) {
        cudaFuncSetAttribute(edge_mma_kernel, cudaFuncAttributeMaxDynamicSharedMemorySize, EDGE_SMEM);
        cudaFuncSetAttribute(lin_mma_kernel,  cudaFuncAttributeMaxDynamicSharedMemorySize, NODE_SMEM);
        cudaFuncSetAttribute(gru_mma_kernel,  cudaFuncAttributeMaxDynamicSharedMemorySize, NODE_SMEM);
        inited = true;
    }

    const int* src = edge_idx;
    const int* dst = edge_idx + N_EDGES;

    conv_w_kernel<<<dim3(576, 5), 256>>>(lin_in_w, msg_w1, msg_w2, gru_wih, gru_whh);
    lin_mma_kernel<<<296, 256, NODE_SMEM>>>(x, lin_in_b);

    for (int l = 0; l < N_LAYERS; l++) {
        zero_agg_kernel<<<(N_NODES * HIDDEN / 4 + 255) / 256, 256>>>();
        edge_mma_kernel<<<148, 256, EDGE_SMEM>>>(
            src, dst, edge_attr, l, msg_b1 + l * 128, msg_b2 + l * 128);
        gru_mma_kernel<<<dim3(296, 6), 256, NODE_SMEM>>>(
            l, gru_bih + (size_t)l * 384, gru_bhh + (size_t)l * 384);
        gru_gate_kernel<<<(N_NODES * HIDDEN + 255) / 256, 256>>>(
            bn_gamma + l * 128, bn_beta + l * 128, bn_mean + l * 128, bn_var + l * 128);
    }

    init_readout_kernel<<<(N_GRAPHS * HIDDEN + 255) / 256, 256>>>();
    seg_reduce_kernel<<<(N_NODES * 32 + 255) / 256, 256>>>(batch);
    readout_kernel<<<N_GRAPHS, 128>>>(ro_w, ro_b, out);
}